// round 13
// baseline (speedup 1.0000x reference)
#include <cuda_runtime.h>
#include <cuda_fp16.h>
#include <cstdint>

// Problem constants
#define H    8
#define M    1024
#define D    64
#define B    8
#define L    2048
#define NTOK 16384
#define TOKC 128       // tokens per CTA
#define GN   128       // codes per group
#define NG   8         // groups
#define KP   72        // padded row length (halves) -> 144B rows, ldmatrix conflict-free

// d_out packing (float32): z_q | vq_loss | indices | new_codebooks
#define ZQ_OFF   ((size_t)0)
#define LOSS_OFF ((size_t)8388608)
#define IDX_OFF  ((size_t)8388609)
#define CB_OFF   ((size_t)8519681)

typedef unsigned int u32;

// Scratch (no allocations allowed -> __device__ globals). Zero at module load;
// re-zeroed at the TAIL of every kernel_launch.
__device__ float g_sums[H * M * D];
__device__ float g_counts[H * M];
__device__ float g_loss;

// ---------------------------------------------------------------------------
struct Smem {
    __half A[2][TOKC][KP];    // z tile hi/lo:      36864 B
    __half Bt[2][GN][KP];     // B group hi/lo:     36864 B
    float cv1[NG * TOKC];
    int   ci1[NG * TOKC];
    float cv2[NG * TOKC];
    int   ci2[NG * TOKC];
    int   sidx[TOKC];
    float red[8];
};

__device__ __forceinline__ u32 smem_u32(const void* p) {
    u32 a;
    asm("{ .reg .u64 t; cvta.to.shared.u64 t, %1; cvt.u32.u64 %0, t; }" : "=r"(a) : "l"(p));
    return a;
}

#define LDSM4(r0, r1, r2, r3, addr) \
    asm volatile("ldmatrix.sync.aligned.m8n8.x4.shared.b16 {%0,%1,%2,%3}, [%4];" \
        : "=r"(r0), "=r"(r1), "=r"(r2), "=r"(r3) : "r"(addr))
#define LDSM2(r0, r1, addr) \
    asm volatile("ldmatrix.sync.aligned.m8n8.x2.shared.b16 {%0,%1}, [%2];" \
        : "=r"(r0), "=r"(r1) : "r"(addr))
#define MMA16816(c0, c1, c2, c3, a0, a1, a2, a3, b0, b1) \
    asm volatile("mma.sync.aligned.m16n8k16.row.col.f32.f16.f16.f32 " \
        "{%0,%1,%2,%3},{%4,%5,%6,%7},{%8,%9},{%0,%1,%2,%3};" \
        : "+f"(c0), "+f"(c1), "+f"(c2), "+f"(c3) \
        : "r"(a0), "r"(a1), "r"(a2), "r"(a3), "r"(b0), "r"(b1))

__device__ __forceinline__ void split_h(float v, __half& hi, __half& lo) {
    hi = __float2half_rn(v);
    lo = __float2half_rn(v - __half2float(hi));
}
__device__ __forceinline__ bool better(float v, int i, float bv, int bi) {
    return v > bv || (v == bv && i < bi);
}
// value-only strict top-2: ties dropped here are within the re-rank margin and
// recovered by the exact fp32 re-rank (which keeps first-index tie-break).
__device__ __forceinline__ void top2(float v, int idx, float& v1, int& i1,
                                     float& v2, int& i2) {
    if (v > v1)      { v2 = v1; i2 = i1; v1 = v; i1 = idx; }
    else if (v > v2) { v2 = v;  i2 = idx; }
}

// ---------------------------------------------------------------------------
__global__ void zero_kernel() {
    int i = blockIdx.x * 256 + threadIdx.x;
    if (i < H * M * D) g_sums[i] = 0.0f;
    if (i < H * M)     g_counts[i] = 0.0f;
    if (i == 0)        g_loss = 0.0f;
}

// ---------------------------------------------------------------------------
// Main kernel: fp16 HMMA sim GEMM (3-pass hi/lo) + per-group top-2 + fp32
// re-rank + fused epilogue. Structure identical to the 399.5us kernel except
// the inner scan uses value-only top2 (fewer issues, fewer live regs).
// ---------------------------------------------------------------------------
__global__ __launch_bounds__(256, 2)
void vq_main(const float* __restrict__ z, const float* __restrict__ cb,
             float* __restrict__ out) {
    extern __shared__ char smraw[];
    Smem& s = *reinterpret_cast<Smem*>(smraw);

    const int tid = threadIdx.x, wid = tid >> 5, lane = tid & 31;
    const int h = blockIdx.y;
    const int n0 = blockIdx.x * TOKC;
    const int b = n0 >> 11, l0 = n0 & (L - 1);
    const float* cbh = cb + (size_t)h * M * D;

    // ---- A tiles: z [64 k x 128 tok] -> fp16 hi/lo, rows = tokens ----
    const size_t zbase = ((size_t)(b * 512 + h * 64)) * (size_t)L + (size_t)l0;
#pragma unroll
    for (int r = 0; r < 8; r++) {
        int f  = tid + 256 * r;
        int k  = f >> 5;
        int t4 = (f & 31) * 4;
        float4 v = *(const float4*)(z + zbase + (size_t)k * L + (size_t)t4);
        float vv[4] = {v.x, v.y, v.z, v.w};
#pragma unroll
        for (int j = 0; j < 4; j++) {
            __half hi, lo;
            split_h(vv[j], hi, lo);
            s.A[0][t4 + j][k] = hi;
            s.A[1][t4 + j][k] = lo;
        }
    }
    __syncthreads();

    // ---- A fragments (m16k16 x 4 ktiles x hi/lo) register-resident ----
    const int tok0 = wid * 16;
    const int ar   = lane & 15;
    const int ac8  = (lane >> 4) << 3;
    u32 af[2][4][4];
#pragma unroll
    for (int hh = 0; hh < 2; hh++)
#pragma unroll
        for (int kt = 0; kt < 4; kt++) {
            u32 addr = smem_u32(&s.A[hh][tok0 + ar][kt * 16 + ac8]);
            LDSM4(af[hh][kt][0], af[hh][kt][1], af[hh][kt][2], af[hh][kt][3], addr);
        }

    // B ldmatrix address lanes (x2): row = code within ntile, col8 select
    const int bn  = lane & 7;
    const int bc8 = ((lane >> 3) & 1) << 3;

    for (int g = 0; g < NG; g++) {
        __syncthreads();
        // ---- load + split B group g: 128 codes x 64 k ----
        {
            int n  = tid >> 1;
            int kh = (tid & 1) * 32;
            const float* src = cbh + (size_t)(g * GN + n) * D + kh;
#pragma unroll
            for (int q = 0; q < 8; q++) {
                float4 v = *(const float4*)(src + q * 4);
                __half h0, l0h, h1, l1, h2, l2, h3, l3;
                split_h(v.x, h0, l0h); split_h(v.y, h1, l1);
                split_h(v.z, h2, l2);  split_h(v.w, h3, l3);
                int k0 = kh + q * 4;
                *(__half2*)&s.Bt[0][n][k0]     = __halves2half2(h0, h1);
                *(__half2*)&s.Bt[0][n][k0 + 2] = __halves2half2(h2, h3);
                *(__half2*)&s.Bt[1][n][k0]     = __halves2half2(l0h, l1);
                *(__half2*)&s.Bt[1][n][k0 + 2] = __halves2half2(l2, l3);
            }
        }
        __syncthreads();

        // ---- MMA over 16 n-tiles; value-only top-2 for the 2 token rows ----
        float v1a = -3.4e38f, v2a = -3.4e38f, v1b = -3.4e38f, v2b = -3.4e38f;
        int   i1a = 0, i2a = 0, i1b = 0, i2b = 0;
#pragma unroll
        for (int nt = 0; nt < 16; nt++) {
            float c0 = 0.f, c1 = 0.f, c2 = 0.f, c3 = 0.f;
#pragma unroll
            for (int kt = 0; kt < 4; kt++) {
                u32 bh0, bh1, bl0, bl1;
                LDSM2(bh0, bh1, smem_u32(&s.Bt[0][nt * 8 + bn][kt * 16 + bc8]));
                LDSM2(bl0, bl1, smem_u32(&s.Bt[1][nt * 8 + bn][kt * 16 + bc8]));
                MMA16816(c0, c1, c2, c3, af[0][kt][0], af[0][kt][1], af[0][kt][2], af[0][kt][3], bh0, bh1);
                MMA16816(c0, c1, c2, c3, af[0][kt][0], af[0][kt][1], af[0][kt][2], af[0][kt][3], bl0, bl1);
                MMA16816(c0, c1, c2, c3, af[1][kt][0], af[1][kt][1], af[1][kt][2], af[1][kt][3], bh0, bh1);
            }
            int code0 = g * GN + nt * 8 + ((lane & 3) << 1);
            top2(c0, code0,     v1a, i1a, v2a, i2a);
            top2(c1, code0 + 1, v1a, i1a, v2a, i2a);
            top2(c2, code0,     v1b, i1b, v2b, i2b);
            top2(c3, code0 + 1, v1b, i1b, v2b, i2b);
        }

        // ---- merge top-2 across the 4 lanes of the quad (full tie-break) ----
#pragma unroll
        for (int off = 1; off < 4; off <<= 1) {
            float w1 = __shfl_xor_sync(0xffffffffu, v1a, off);
            int   j1 = __shfl_xor_sync(0xffffffffu, i1a, off);
            float w2 = __shfl_xor_sync(0xffffffffu, v2a, off);
            int   j2 = __shfl_xor_sync(0xffffffffu, i2a, off);
            if (better(w1, j1, v1a, i1a)) {
                if (better(v1a, i1a, w2, j2)) { v2a = v1a; i2a = i1a; }
                else                          { v2a = w2;  i2a = j2;  }
                v1a = w1; i1a = j1;
            } else if (better(w1, j1, v2a, i2a)) { v2a = w1; i2a = j1; }

            w1 = __shfl_xor_sync(0xffffffffu, v1b, off);
            j1 = __shfl_xor_sync(0xffffffffu, i1b, off);
            w2 = __shfl_xor_sync(0xffffffffu, v2b, off);
            j2 = __shfl_xor_sync(0xffffffffu, i2b, off);
            if (better(w1, j1, v1b, i1b)) {
                if (better(v1b, i1b, w2, j2)) { v2b = v1b; i2b = i1b; }
                else                          { v2b = w2;  i2b = j2;  }
                v1b = w1; i1b = j1;
            } else if (better(w1, j1, v2b, i2b)) { v2b = w1; i2b = j1; }
        }
        if ((lane & 3) == 0) {
            int tokA = tok0 + (lane >> 2);
            s.cv1[g * TOKC + tokA] = v1a;  s.ci1[g * TOKC + tokA] = i1a;
            s.cv2[g * TOKC + tokA] = v2a;  s.ci2[g * TOKC + tokA] = i2a;
            int tokB = tokA + 8;
            s.cv1[g * TOKC + tokB] = v1b;  s.ci1[g * TOKC + tokB] = i1b;
            s.cv2[g * TOKC + tokB] = v2b;  s.ci2[g * TOKC + tokB] = i2b;
        }
    }
    __syncthreads();

    // ---- fp32 re-rank of candidates within margin of approx max ----
    if (tid < TOKC) {
        const int t = tid;
        float gmax = -3.4e38f;
#pragma unroll
        for (int g = 0; g < NG; g++)
            gmax = fmaxf(gmax, s.cv1[g * TOKC + t]);
        const float thr = gmax - 0.01f;   // margin >> fp16 3-pass error (~1e-5)
        int cidx[16];
        int cnt = 0;
#pragma unroll
        for (int g = 0; g < NG; g++) {
            if (s.cv1[g * TOKC + t] >= thr) cidx[cnt++] = s.ci1[g * TOKC + t];
            if (s.cv2[g * TOKC + t] >= thr) cidx[cnt++] = s.ci2[g * TOKC + t];
        }
        int m;
        if (cnt == 1) {
            m = cidx[0];
        } else {
            float bestv = -3.4e38f;
            m = 1 << 30;
            for (int j = 0; j < cnt; j++) {
                int idx = cidx[j];
                const float* crow = cbh + (size_t)idx * D;
                float dot = 0.0f;
#pragma unroll
                for (int k = 0; k < D; k++) {
                    float zv = __half2float(s.A[0][t][k]) + __half2float(s.A[1][t][k]);
                    dot += zv * __ldg(crow + k);
                }
                if (dot > bestv || (dot == bestv && idx < m)) { bestv = dot; m = idx; }
            }
        }
        s.sidx[t] = m;
        out[IDX_OFF + ((size_t)b * H + (size_t)h) * (size_t)L + (size_t)(l0 + t)] = (float)m;
        atomicAdd(&g_counts[h * M + m], 1.0f);
    }
    __syncthreads();

    // ---- epilogue: z_q, loss, segment sums (z = hi + lo, 2e-7 rel err) ----
    float lsum = 0.0f;
#pragma unroll
    for (int i = 0; i < 32; i++) {
        int e = i * 256 + tid;
        int k = e >> 7;
        int t = e & 127;
        int mm = s.sidx[t];
        float zv = __half2float(s.A[0][t][k]) + __half2float(s.A[1][t][k]);
        float c = __ldg(cbh + (size_t)mm * D + k);
        size_t o = ((size_t)(b * 512 + h * 64 + k)) * (size_t)L + (size_t)(l0 + t);
        out[ZQ_OFF + o] = c;
        float dd = zv - c;
        lsum += dd * dd;
        atomicAdd(&g_sums[(h * M + mm) * D + k], zv);
    }
#pragma unroll
    for (int o = 16; o > 0; o >>= 1)
        lsum += __shfl_xor_sync(0xffffffffu, lsum, o);
    if (lane == 0) s.red[wid] = lsum;
    __syncthreads();
    if (tid == 0) {
        float tt = 0.0f;
#pragma unroll
        for (int w = 0; w < 8; w++) tt += s.red[w];
        atomicAdd(&g_loss, tt);
    }
}

// ---------------------------------------------------------------------------
// Update kernel: slerp + rms_norm codebook EMA (1 warp per code) + vq_loss.
// ---------------------------------------------------------------------------
__global__ void vq_update(const float* __restrict__ cb, float* __restrict__ out) {
    if (blockIdx.x == 0 && threadIdx.x == 0)
        out[LOSS_OFF] = 1.25f * g_loss * (1.0f / 8388608.0f);

    const int code = blockIdx.x * 8 + (threadIdx.x >> 5);
    const int lane = threadIdx.x & 31;
    if (code >= H * M) return;

    const float* old = cb + (size_t)code * D;
    float o0 = old[lane];
    float o1 = old[lane + 32];
    float cnt = g_counts[code];
    float r0, r1;

    if (cnt > 0.0f) {
        float m0 = g_sums[code * D + lane] / cnt;
        float m1 = g_sums[code * D + lane + 32] / cnt;

        float dot = m0 * o0 + m1 * o1;
        float nl  = m0 * m0 + m1 * m1;
        float nh  = o0 * o0 + o1 * o1;
#pragma unroll
        for (int o = 16; o > 0; o >>= 1) {
            dot += __shfl_xor_sync(0xffffffffu, dot, o);
            nl  += __shfl_xor_sync(0xffffffffu, nl,  o);
            nh  += __shfl_xor_sync(0xffffffffu, nh,  o);
        }
        float cosv = dot / fmaxf(sqrtf(nl) * sqrtf(nh), 1e-8f);
        cosv = fminf(fmaxf(cosv, (float)(-1.0 + 1e-7)), (float)(1.0 - 1e-7));
        float omega = acosf(cosv);
        float so = sinf(omega);
        float wl = sinf(0.01f * omega);
        float wh = sinf(0.99f * omega);
        r0 = (m0 * wl + o0 * wh) / so;
        r1 = (m1 * wl + o1 * wh) / so;

        float ss = r0 * r0 + r1 * r1;
#pragma unroll
        for (int o = 16; o > 0; o >>= 1)
            ss += __shfl_xor_sync(0xffffffffu, ss, o);
        float inv = 1.0f / sqrtf(ss * (1.0f / 64.0f) + 1.1920929e-07f);
        r0 *= inv;
        r1 *= inv;
    } else {
        r0 = o0;
        r1 = o1;
    }

    out[CB_OFF + (size_t)code * D + lane]      = r0;
    out[CB_OFF + (size_t)code * D + lane + 32] = r1;
}

// ---------------------------------------------------------------------------
extern "C" void kernel_launch(void* const* d_in, const int* in_sizes, int n_in,
                              void* d_out, int out_size) {
    const float* z  = (const float*)d_in[0];   // [8, 512, 2048]
    const float* cb = (const float*)d_in[1];   // [8, 1024, 64]
    float* out = (float*)d_out;

    cudaFuncSetAttribute(vq_main, cudaFuncAttributeMaxDynamicSharedMemorySize,
                         (int)sizeof(Smem));

    dim3 grid(NTOK / TOKC, H);
    vq_main<<<grid, 256, sizeof(Smem)>>>(z, cb, out);

    vq_update<<<H * M / 8, 256>>>(cb, out);

    // Reset scratch for the NEXT invocation (initial state is zero at load).
    zero_kernel<<<(H * M * D + 255) / 256, 256>>>();
}

// round 15
// speedup vs baseline: 1.9147x; 1.9147x over previous
#include <cuda_runtime.h>
#include <cuda_fp16.h>
#include <cstdint>

// Problem constants
#define H    8
#define M    1024
#define D    64
#define B    8
#define L    2048
#define NTOK 16384
#define TOKC 128       // tokens per CTA
#define GN   128       // codes per group
#define NG   8         // groups
#define KP   72        // padded row length (halves) -> 144B rows, ldmatrix conflict-free

// d_out packing (float32): z_q | vq_loss | indices | new_codebooks
#define ZQ_OFF   ((size_t)0)
#define LOSS_OFF ((size_t)8388608)
#define IDX_OFF  ((size_t)8388609)
#define CB_OFF   ((size_t)8519681)

typedef unsigned int u32;

// Scratch (no allocations allowed -> __device__ globals). Zero at module load;
// re-zeroed at the TAIL of every kernel_launch.
__device__ float g_sums[H * M * D];
__device__ float g_counts[H * M];
__device__ float g_loss;

// ---------------------------------------------------------------------------
struct Smem {
    __half A[2][TOKC][KP];    // z tile hi/lo:      36864 B
    __half Bt[2][GN][KP];     // B group hi/lo:     36864 B
    float cv1[NG * TOKC];     // per-group max value
    int   ci1[NG * TOKC];     // per-group argmax
    int   sidx[TOKC];
    float red[8];
};

__device__ __forceinline__ u32 smem_u32(const void* p) {
    u32 a;
    asm("{ .reg .u64 t; cvta.to.shared.u64 t, %1; cvt.u32.u64 %0, t; }" : "=r"(a) : "l"(p));
    return a;
}

#define LDSM4(r0, r1, r2, r3, addr) \
    asm volatile("ldmatrix.sync.aligned.m8n8.x4.shared.b16 {%0,%1,%2,%3}, [%4];" \
        : "=r"(r0), "=r"(r1), "=r"(r2), "=r"(r3) : "r"(addr))
#define LDSM2(r0, r1, addr) \
    asm volatile("ldmatrix.sync.aligned.m8n8.x2.shared.b16 {%0,%1}, [%2];" \
        : "=r"(r0), "=r"(r1) : "r"(addr))
#define MMA16816(c0, c1, c2, c3, a0, a1, a2, a3, b0, b1) \
    asm volatile("mma.sync.aligned.m16n8k16.row.col.f32.f16.f16.f32 " \
        "{%0,%1,%2,%3},{%4,%5,%6,%7},{%8,%9},{%0,%1,%2,%3};" \
        : "+f"(c0), "+f"(c1), "+f"(c2), "+f"(c3) \
        : "r"(a0), "r"(a1), "r"(a2), "r"(a3), "r"(b0), "r"(b1))

__device__ __forceinline__ void split_h(float v, __half& hi, __half& lo) {
    hi = __float2half_rn(v);
    lo = __float2half_rn(v - __half2float(hi));
}
// branchless max+argmax update (FSETP + SEL + FMNMX, no branches)
__device__ __forceinline__ void amax(float v, int idx, float& v1, int& i1) {
    bool p = v > v1;
    i1 = p ? idx : i1;
    v1 = fmaxf(v1, v);
}

// ---------------------------------------------------------------------------
__global__ void zero_kernel() {
    int i = blockIdx.x * 256 + threadIdx.x;
    if (i < H * M * D) g_sums[i] = 0.0f;
    if (i < H * M)     g_counts[i] = 0.0f;
    if (i == 0)        g_loss = 0.0f;
}

// ---------------------------------------------------------------------------
// Main kernel: fp16 HMMA sim GEMM (3-pass hi/lo) + branchless per-group argmax
// + fp32 re-rank + fused epilogue.
// ---------------------------------------------------------------------------
__global__ __launch_bounds__(256, 2)
void vq_main(const float* __restrict__ z, const float* __restrict__ cb,
             float* __restrict__ out) {
    extern __shared__ char smraw[];
    Smem& s = *reinterpret_cast<Smem*>(smraw);

    const int tid = threadIdx.x, wid = tid >> 5, lane = tid & 31;
    const int h = blockIdx.y;
    const int n0 = blockIdx.x * TOKC;
    const int b = n0 >> 11, l0 = n0 & (L - 1);
    const float* cbh = cb + (size_t)h * M * D;

    // ---- A tiles: z [64 k x 128 tok] -> fp16 hi/lo, rows = tokens ----
    const size_t zbase = ((size_t)(b * 512 + h * 64)) * (size_t)L + (size_t)l0;
#pragma unroll
    for (int r = 0; r < 8; r++) {
        int f  = tid + 256 * r;
        int k  = f >> 5;
        int t4 = (f & 31) * 4;
        float4 v = *(const float4*)(z + zbase + (size_t)k * L + (size_t)t4);
        float vv[4] = {v.x, v.y, v.z, v.w};
#pragma unroll
        for (int j = 0; j < 4; j++) {
            __half hi, lo;
            split_h(vv[j], hi, lo);
            s.A[0][t4 + j][k] = hi;
            s.A[1][t4 + j][k] = lo;
        }
    }
    __syncthreads();

    // ---- A fragments (m16k16 x 4 ktiles x hi/lo) register-resident ----
    const int tok0 = wid * 16;
    const int ar   = lane & 15;
    const int ac8  = (lane >> 4) << 3;
    u32 af[2][4][4];
#pragma unroll
    for (int hh = 0; hh < 2; hh++)
#pragma unroll
        for (int kt = 0; kt < 4; kt++) {
            u32 addr = smem_u32(&s.A[hh][tok0 + ar][kt * 16 + ac8]);
            LDSM4(af[hh][kt][0], af[hh][kt][1], af[hh][kt][2], af[hh][kt][3], addr);
        }

    // B ldmatrix address lanes (x2): row = code within ntile, col8 select
    const int bn  = lane & 7;
    const int bc8 = ((lane >> 3) & 1) << 3;

    for (int g = 0; g < NG; g++) {
        __syncthreads();
        // ---- load + split B group g: 128 codes x 64 k ----
        {
            int n  = tid >> 1;
            int kh = (tid & 1) * 32;
            const float* src = cbh + (size_t)(g * GN + n) * D + kh;
#pragma unroll
            for (int q = 0; q < 8; q++) {
                float4 v = *(const float4*)(src + q * 4);
                __half h0, l0h, h1, l1, h2, l2, h3, l3;
                split_h(v.x, h0, l0h); split_h(v.y, h1, l1);
                split_h(v.z, h2, l2);  split_h(v.w, h3, l3);
                int k0 = kh + q * 4;
                *(__half2*)&s.Bt[0][n][k0]     = __halves2half2(h0, h1);
                *(__half2*)&s.Bt[0][n][k0 + 2] = __halves2half2(h2, h3);
                *(__half2*)&s.Bt[1][n][k0]     = __halves2half2(l0h, l1);
                *(__half2*)&s.Bt[1][n][k0 + 2] = __halves2half2(l2, l3);
            }
        }
        __syncthreads();

        // ---- MMA over 16 n-tiles; branchless max+argmax per token row ----
        float v1a = -3.4e38f, v1b = -3.4e38f;
        int   i1a = 0, i1b = 0;
#pragma unroll
        for (int nt = 0; nt < 16; nt++) {
            float c0 = 0.f, c1 = 0.f, c2 = 0.f, c3 = 0.f;
#pragma unroll
            for (int kt = 0; kt < 4; kt++) {
                u32 bh0, bh1, bl0, bl1;
                LDSM2(bh0, bh1, smem_u32(&s.Bt[0][nt * 8 + bn][kt * 16 + bc8]));
                LDSM2(bl0, bl1, smem_u32(&s.Bt[1][nt * 8 + bn][kt * 16 + bc8]));
                MMA16816(c0, c1, c2, c3, af[0][kt][0], af[0][kt][1], af[0][kt][2], af[0][kt][3], bh0, bh1);
                MMA16816(c0, c1, c2, c3, af[0][kt][0], af[0][kt][1], af[0][kt][2], af[0][kt][3], bl0, bl1);
                MMA16816(c0, c1, c2, c3, af[1][kt][0], af[1][kt][1], af[1][kt][2], af[1][kt][3], bh0, bh1);
            }
            int code0 = g * GN + nt * 8 + ((lane & 3) << 1);
            amax(c0, code0,     v1a, i1a);
            amax(c1, code0 + 1, v1a, i1a);
            amax(c2, code0,     v1b, i1b);
            amax(c3, code0 + 1, v1b, i1b);
        }

        // ---- merge argmax across the 4 lanes of the quad (branchless) ----
#pragma unroll
        for (int off = 1; off < 4; off <<= 1) {
            float w = __shfl_xor_sync(0xffffffffu, v1a, off);
            int   j = __shfl_xor_sync(0xffffffffu, i1a, off);
            bool p = (w > v1a) || (w == v1a && j < i1a);
            v1a = p ? w : v1a;
            i1a = p ? j : i1a;

            w = __shfl_xor_sync(0xffffffffu, v1b, off);
            j = __shfl_xor_sync(0xffffffffu, i1b, off);
            p = (w > v1b) || (w == v1b && j < i1b);
            v1b = p ? w : v1b;
            i1b = p ? j : i1b;
        }
        if ((lane & 3) == 0) {
            int tokA = tok0 + (lane >> 2);
            s.cv1[g * TOKC + tokA] = v1a;  s.ci1[g * TOKC + tokA] = i1a;
            int tokB = tokA + 8;
            s.cv1[g * TOKC + tokB] = v1b;  s.ci1[g * TOKC + tokB] = i1b;
        }
    }
    __syncthreads();

    // ---- fp32 re-rank of group-max candidates within margin ----
    if (tid < TOKC) {
        const int t = tid;
        float gmax = -3.4e38f;
#pragma unroll
        for (int g = 0; g < NG; g++)
            gmax = fmaxf(gmax, s.cv1[g * TOKC + t]);
        const float thr = gmax - 0.01f;   // margin >> fp16 3-pass error (~1e-5)
        int cidx[NG];
        int cnt = 0;
#pragma unroll
        for (int g = 0; g < NG; g++) {
            if (s.cv1[g * TOKC + t] >= thr) cidx[cnt++] = s.ci1[g * TOKC + t];
        }
        int m;
        if (cnt == 1) {
            m = cidx[0];
        } else {
            float bestv = -3.4e38f;
            m = 1 << 30;
            for (int j = 0; j < cnt; j++) {
                int idx = cidx[j];
                const float* crow = cbh + (size_t)idx * D;
                float dot = 0.0f;
#pragma unroll
                for (int k = 0; k < D; k++) {
                    float zv = __half2float(s.A[0][t][k]) + __half2float(s.A[1][t][k]);
                    dot += zv * __ldg(crow + k);
                }
                if (dot > bestv || (dot == bestv && idx < m)) { bestv = dot; m = idx; }
            }
        }
        s.sidx[t] = m;
        out[IDX_OFF + ((size_t)b * H + (size_t)h) * (size_t)L + (size_t)(l0 + t)] = (float)m;
        atomicAdd(&g_counts[h * M + m], 1.0f);
    }
    __syncthreads();

    // ---- epilogue: z_q, loss, segment sums (z = hi + lo, 2e-7 rel err) ----
    float lsum = 0.0f;
#pragma unroll
    for (int i = 0; i < 32; i++) {
        int e = i * 256 + tid;
        int k = e >> 7;
        int t = e & 127;
        int mm = s.sidx[t];
        float zv = __half2float(s.A[0][t][k]) + __half2float(s.A[1][t][k]);
        float c = __ldg(cbh + (size_t)mm * D + k);
        size_t o = ((size_t)(b * 512 + h * 64 + k)) * (size_t)L + (size_t)(l0 + t);
        out[ZQ_OFF + o] = c;
        float dd = zv - c;
        lsum += dd * dd;
        atomicAdd(&g_sums[(h * M + mm) * D + k], zv);
    }
#pragma unroll
    for (int o = 16; o > 0; o >>= 1)
        lsum += __shfl_xor_sync(0xffffffffu, lsum, o);
    if (lane == 0) s.red[wid] = lsum;
    __syncthreads();
    if (tid == 0) {
        float tt = 0.0f;
#pragma unroll
        for (int w = 0; w < 8; w++) tt += s.red[w];
        atomicAdd(&g_loss, tt);
    }
}

// ---------------------------------------------------------------------------
// Update kernel: slerp + rms_norm codebook EMA (1 warp per code) + vq_loss.
// ---------------------------------------------------------------------------
__global__ void vq_update(const float* __restrict__ cb, float* __restrict__ out) {
    if (blockIdx.x == 0 && threadIdx.x == 0)
        out[LOSS_OFF] = 1.25f * g_loss * (1.0f / 8388608.0f);

    const int code = blockIdx.x * 8 + (threadIdx.x >> 5);
    const int lane = threadIdx.x & 31;
    if (code >= H * M) return;

    const float* old = cb + (size_t)code * D;
    float o0 = old[lane];
    float o1 = old[lane + 32];
    float cnt = g_counts[code];
    float r0, r1;

    if (cnt > 0.0f) {
        float m0 = g_sums[code * D + lane] / cnt;
        float m1 = g_sums[code * D + lane + 32] / cnt;

        float dot = m0 * o0 + m1 * o1;
        float nl  = m0 * m0 + m1 * m1;
        float nh  = o0 * o0 + o1 * o1;
#pragma unroll
        for (int o = 16; o > 0; o >>= 1) {
            dot += __shfl_xor_sync(0xffffffffu, dot, o);
            nl  += __shfl_xor_sync(0xffffffffu, nl,  o);
            nh  += __shfl_xor_sync(0xffffffffu, nh,  o);
        }
        float cosv = dot / fmaxf(sqrtf(nl) * sqrtf(nh), 1e-8f);
        cosv = fminf(fmaxf(cosv, (float)(-1.0 + 1e-7)), (float)(1.0 - 1e-7));
        float omega = acosf(cosv);
        float so = sinf(omega);
        float wl = sinf(0.01f * omega);
        float wh = sinf(0.99f * omega);
        r0 = (m0 * wl + o0 * wh) / so;
        r1 = (m1 * wl + o1 * wh) / so;

        float ss = r0 * r0 + r1 * r1;
#pragma unroll
        for (int o = 16; o > 0; o >>= 1)
            ss += __shfl_xor_sync(0xffffffffu, ss, o);
        float inv = 1.0f / sqrtf(ss * (1.0f / 64.0f) + 1.1920929e-07f);
        r0 *= inv;
        r1 *= inv;
    } else {
        r0 = o0;
        r1 = o1;
    }

    out[CB_OFF + (size_t)code * D + lane]      = r0;
    out[CB_OFF + (size_t)code * D + lane + 32] = r1;
}

// ---------------------------------------------------------------------------
extern "C" void kernel_launch(void* const* d_in, const int* in_sizes, int n_in,
                              void* d_out, int out_size) {
    const float* z  = (const float*)d_in[0];   // [8, 512, 2048]
    const float* cb = (const float*)d_in[1];   // [8, 1024, 64]
    float* out = (float*)d_out;

    cudaFuncSetAttribute(vq_main, cudaFuncAttributeMaxDynamicSharedMemorySize,
                         (int)sizeof(Smem));

    dim3 grid(NTOK / TOKC, H);
    vq_main<<<grid, 256, sizeof(Smem)>>>(z, cb, out);

    vq_update<<<H * M / 8, 256>>>(cb, out);

    // Reset scratch for the NEXT invocation (initial state is zero at load).
    zero_kernel<<<(H * M * D + 255) / 256, 256>>>();
}

// round 16
// speedup vs baseline: 2.5043x; 1.3079x over previous
#include <cuda_runtime.h>
#include <cuda_fp16.h>
#include <cstdint>

// Problem constants
#define H    8
#define M    1024
#define D    64
#define B    8
#define L    2048
#define NTOK 16384
#define TOKC 128       // tokens per CTA
#define GN   128       // codes per group
#define NG   8         // groups
#define KP   72        // A-tile padded row (halves) -> 144B rows, ldmatrix conflict-free

// d_out packing (float32): z_q | vq_loss | indices | new_codebooks
#define ZQ_OFF   ((size_t)0)
#define LOSS_OFF ((size_t)8388608)
#define IDX_OFF  ((size_t)8388609)
#define CB_OFF   ((size_t)8519681)

typedef unsigned int u32;

// Scratch (no allocations allowed -> __device__ globals). Zero at module load;
// re-zeroed at the TAIL of every kernel_launch.
__device__ float g_sums[H * M * D];
__device__ float g_counts[H * M];
__device__ float g_loss;
// Pre-split codebook: [h][g][hh][row 128][chunk 8 (swizzled)][8 halves] = 2 MB
__device__ __half g_bsplit[H * NG * 2 * GN * 64];

// ---------------------------------------------------------------------------
struct Smem {
    __half A[2][TOKC][KP];        // z tile hi/lo:            36864 B
    __half Bt[2][2][GN][64];      // B buffers [buf][hh], swizzled rows: 65536 B
    float cv1[NG * TOKC];         // per-group max value       4096 B
    int   ci1[NG * TOKC];         // per-group argmax          4096 B
    int   sidx[TOKC];
    float red[8];
};                                 // total ~111.1 KB -> 2 CTAs/SM

__device__ __forceinline__ u32 smem_u32(const void* p) {
    u32 a;
    asm("{ .reg .u64 t; cvta.to.shared.u64 t, %1; cvt.u32.u64 %0, t; }" : "=r"(a) : "l"(p));
    return a;
}

#define LDSM4(r0, r1, r2, r3, addr) \
    asm volatile("ldmatrix.sync.aligned.m8n8.x4.shared.b16 {%0,%1,%2,%3}, [%4];" \
        : "=r"(r0), "=r"(r1), "=r"(r2), "=r"(r3) : "r"(addr))
#define LDSM2(r0, r1, addr) \
    asm volatile("ldmatrix.sync.aligned.m8n8.x2.shared.b16 {%0,%1}, [%2];" \
        : "=r"(r0), "=r"(r1) : "r"(addr))
#define MMA16816(c0, c1, c2, c3, a0, a1, a2, a3, b0, b1) \
    asm volatile("mma.sync.aligned.m16n8k16.row.col.f32.f16.f16.f32 " \
        "{%0,%1,%2,%3},{%4,%5,%6,%7},{%8,%9},{%0,%1,%2,%3};" \
        : "+f"(c0), "+f"(c1), "+f"(c2), "+f"(c3) \
        : "r"(a0), "r"(a1), "r"(a2), "r"(a3), "r"(b0), "r"(b1))
#define CP_COMMIT() asm volatile("cp.async.commit_group;" ::: "memory")
#define CP_WAIT0()  asm volatile("cp.async.wait_group 0;" ::: "memory")

__device__ __forceinline__ void split_h(float v, __half& hi, __half& lo) {
    hi = __float2half_rn(v);
    lo = __float2half_rn(v - __half2float(hi));
}
// branchless max+argmax update (FSETP + SEL + FMNMX, no branches)
__device__ __forceinline__ void amax(float v, int idx, float& v1, int& i1) {
    bool p = v > v1;
    i1 = p ? idx : i1;
    v1 = fmaxf(v1, v);
}

// ---------------------------------------------------------------------------
__global__ void zero_kernel() {
    int i = blockIdx.x * 256 + threadIdx.x;
    if (i < H * M * D) g_sums[i] = 0.0f;
    if (i < H * M)     g_counts[i] = 0.0f;
    if (i == 0)        g_loss = 0.0f;
}

// ---------------------------------------------------------------------------
// Prep kernel: split codebook fp32 -> fp16 hi/lo in the exact smem tile layout
// (16B-chunk swizzle baked in), so vq_main can cp.async it verbatim.
// One thread = one 16B output chunk (8 halves). 131072 chunks total.
// ---------------------------------------------------------------------------
__global__ void prep_b(const float* __restrict__ cb) {
    int cid = blockIdx.x * 256 + threadIdx.x;
    int chunk = cid & 7;
    int row   = (cid >> 3) & 127;
    int hh    = (cid >> 10) & 1;
    int g     = (cid >> 11) & 7;
    int h     = cid >> 14;

    const float* src = cb + ((size_t)(h * M) + (size_t)(g * GN + row)) * D + chunk * 8;
    float4 v0 = *(const float4*)(src);
    float4 v1 = *(const float4*)(src + 4);
    float vv[8] = {v0.x, v0.y, v0.z, v0.w, v1.x, v1.y, v1.z, v1.w};
    __half o[8];
#pragma unroll
    for (int j = 0; j < 8; j++) {
        __half hi = __float2half_rn(vv[j]);
        o[j] = hh ? __float2half_rn(vv[j] - __half2float(hi)) : hi;
    }
    size_t dst = ((size_t)((((h * 8 + g) * 2 + hh) * GN + row) * 8 + (chunk ^ (row & 7)))) * 8;
    *(uint4*)(g_bsplit + dst) = *(uint4*)o;
}

// issue one B group's copies: 2048 chunks of 16B, 8 per thread
__device__ __forceinline__ void cp_group(u32 smem_base, const __half* gsrc, int tid) {
#pragma unroll
    for (int j = 0; j < 8; j++) {
        int c = tid + j * 256;
        asm volatile("cp.async.cg.shared.global [%0], [%1], 16;"
            :: "r"(smem_base + c * 16), "l"(gsrc + (size_t)c * 8) : "memory");
    }
}

// ---------------------------------------------------------------------------
// Main kernel: fp16 HMMA sim GEMM (3-pass hi/lo) + branchless per-group argmax
// + fp32 re-rank + fused epilogue. B tiles pre-split in gmem, streamed via
// cp.async double buffer: copy of group g+1 overlaps MMA of group g.
// ---------------------------------------------------------------------------
__global__ __launch_bounds__(256, 2)
void vq_main(const float* __restrict__ z, const float* __restrict__ cb,
             float* __restrict__ out) {
    extern __shared__ char smraw[];
    Smem& s = *reinterpret_cast<Smem*>(smraw);

    const int tid = threadIdx.x, wid = tid >> 5, lane = tid & 31;
    const int h = blockIdx.y;
    const int n0 = blockIdx.x * TOKC;
    const int b = n0 >> 11, l0 = n0 & (L - 1);
    const float* cbh = cb + (size_t)h * M * D;
    const __half* bsrc = g_bsplit + (size_t)h * (NG * 2 * GN * 64);

    // ---- prologue: start copy of B group 0 ----
    const u32 bt0 = smem_u32(&s.Bt[0][0][0][0]);
    const u32 bt1 = smem_u32(&s.Bt[1][0][0][0]);
    cp_group(bt0, bsrc, tid);
    CP_COMMIT();

    // ---- A tiles: z [64 k x 128 tok] -> fp16 hi/lo, rows = tokens ----
    const size_t zbase = ((size_t)(b * 512 + h * 64)) * (size_t)L + (size_t)l0;
#pragma unroll
    for (int r = 0; r < 8; r++) {
        int f  = tid + 256 * r;
        int k  = f >> 5;
        int t4 = (f & 31) * 4;
        float4 v = *(const float4*)(z + zbase + (size_t)k * L + (size_t)t4);
        float vv[4] = {v.x, v.y, v.z, v.w};
#pragma unroll
        for (int j = 0; j < 4; j++) {
            __half hi, lo;
            split_h(vv[j], hi, lo);
            s.A[0][t4 + j][k] = hi;
            s.A[1][t4 + j][k] = lo;
        }
    }
    __syncthreads();

    // ---- A fragments (m16k16 x 4 ktiles x hi/lo) register-resident ----
    const int tok0 = wid * 16;
    const int ar   = lane & 15;
    const int ac8  = (lane >> 4) << 3;
    u32 af[2][4][4];
#pragma unroll
    for (int hh = 0; hh < 2; hh++)
#pragma unroll
        for (int kt = 0; kt < 4; kt++) {
            u32 addr = smem_u32(&s.A[hh][tok0 + ar][kt * 16 + ac8]);
            LDSM4(af[hh][kt][0], af[hh][kt][1], af[hh][kt][2], af[hh][kt][3], addr);
        }

    // B ldmatrix lanes: row = nt*8 + bn; 16B chunk = (2*kt + cb1) ^ bn (swizzled)
    const int bn  = lane & 7;
    const int cb1 = (lane >> 3) & 1;

    for (int g = 0; g < NG; g++) {
        const u32 bufb = (g & 1) ? bt1 : bt0;
        CP_WAIT0();          // this thread's copies of group g complete
        __syncthreads();     // everyone's copies visible; prev MMA done -> other buf free
        if (g + 1 < NG) {
            cp_group((g & 1) ? bt0 : bt1, bsrc + (size_t)(g + 1) * 16384, tid);
            CP_COMMIT();     // overlaps with MMA below
        }

        // ---- MMA over 16 n-tiles; branchless max+argmax per token row ----
        float v1a = -3.4e38f, v1b = -3.4e38f;
        int   i1a = 0, i1b = 0;
#pragma unroll
        for (int nt = 0; nt < 16; nt++) {
            const u32 rowb_h = bufb + (u32)(nt * 8 + bn) * 128;
            const u32 rowb_l = rowb_h + 16384;
            float c0 = 0.f, c1 = 0.f, c2 = 0.f, c3 = 0.f;
#pragma unroll
            for (int kt = 0; kt < 4; kt++) {
                const u32 coff = (u32)(((2 * kt + cb1) ^ bn) * 16);
                u32 bh0, bh1, bl0, bl1;
                LDSM2(bh0, bh1, rowb_h + coff);
                LDSM2(bl0, bl1, rowb_l + coff);
                MMA16816(c0, c1, c2, c3, af[0][kt][0], af[0][kt][1], af[0][kt][2], af[0][kt][3], bh0, bh1);
                MMA16816(c0, c1, c2, c3, af[0][kt][0], af[0][kt][1], af[0][kt][2], af[0][kt][3], bl0, bl1);
                MMA16816(c0, c1, c2, c3, af[1][kt][0], af[1][kt][1], af[1][kt][2], af[1][kt][3], bh0, bh1);
            }
            int code0 = g * GN + nt * 8 + ((lane & 3) << 1);
            amax(c0, code0,     v1a, i1a);
            amax(c1, code0 + 1, v1a, i1a);
            amax(c2, code0,     v1b, i1b);
            amax(c3, code0 + 1, v1b, i1b);
        }

        // ---- merge argmax across the 4 lanes of the quad (branchless) ----
#pragma unroll
        for (int off = 1; off < 4; off <<= 1) {
            float w = __shfl_xor_sync(0xffffffffu, v1a, off);
            int   j = __shfl_xor_sync(0xffffffffu, i1a, off);
            bool p = (w > v1a) || (w == v1a && j < i1a);
            v1a = p ? w : v1a;
            i1a = p ? j : i1a;

            w = __shfl_xor_sync(0xffffffffu, v1b, off);
            j = __shfl_xor_sync(0xffffffffu, i1b, off);
            p = (w > v1b) || (w == v1b && j < i1b);
            v1b = p ? w : v1b;
            i1b = p ? j : i1b;
        }
        if ((lane & 3) == 0) {
            int tokA = tok0 + (lane >> 2);
            s.cv1[g * TOKC + tokA] = v1a;  s.ci1[g * TOKC + tokA] = i1a;
            int tokB = tokA + 8;
            s.cv1[g * TOKC + tokB] = v1b;  s.ci1[g * TOKC + tokB] = i1b;
        }
    }
    __syncthreads();

    // ---- fp32 re-rank of group-max candidates within margin ----
    if (tid < TOKC) {
        const int t = tid;
        float gmax = -3.4e38f;
#pragma unroll
        for (int g = 0; g < NG; g++)
            gmax = fmaxf(gmax, s.cv1[g * TOKC + t]);
        const float thr = gmax - 0.01f;   // margin >> fp16 3-pass error (~1e-5)
        int cidx[NG];
        int cnt = 0;
#pragma unroll
        for (int g = 0; g < NG; g++) {
            if (s.cv1[g * TOKC + t] >= thr) cidx[cnt++] = s.ci1[g * TOKC + t];
        }
        int m;
        if (cnt == 1) {
            m = cidx[0];
        } else {
            float bestv = -3.4e38f;
            m = 1 << 30;
            for (int j = 0; j < cnt; j++) {
                int idx = cidx[j];
                const float* crow = cbh + (size_t)idx * D;
                float dot = 0.0f;
#pragma unroll
                for (int k = 0; k < D; k++) {
                    float zv = __half2float(s.A[0][t][k]) + __half2float(s.A[1][t][k]);
                    dot += zv * __ldg(crow + k);
                }
                if (dot > bestv || (dot == bestv && idx < m)) { bestv = dot; m = idx; }
            }
        }
        s.sidx[t] = m;
        out[IDX_OFF + ((size_t)b * H + (size_t)h) * (size_t)L + (size_t)(l0 + t)] = (float)m;
        atomicAdd(&g_counts[h * M + m], 1.0f);
    }
    __syncthreads();

    // ---- epilogue: z_q, loss, segment sums (z = hi + lo, 2e-7 rel err) ----
    float lsum = 0.0f;
#pragma unroll
    for (int i = 0; i < 32; i++) {
        int e = i * 256 + tid;
        int k = e >> 7;
        int t = e & 127;
        int mm = s.sidx[t];
        float zv = __half2float(s.A[0][t][k]) + __half2float(s.A[1][t][k]);
        float c = __ldg(cbh + (size_t)mm * D + k);
        size_t o = ((size_t)(b * 512 + h * 64 + k)) * (size_t)L + (size_t)(l0 + t);
        out[ZQ_OFF + o] = c;
        float dd = zv - c;
        lsum += dd * dd;
        atomicAdd(&g_sums[(h * M + mm) * D + k], zv);
    }
#pragma unroll
    for (int o = 16; o > 0; o >>= 1)
        lsum += __shfl_xor_sync(0xffffffffu, lsum, o);
    if (lane == 0) s.red[wid] = lsum;
    __syncthreads();
    if (tid == 0) {
        float tt = 0.0f;
#pragma unroll
        for (int w = 0; w < 8; w++) tt += s.red[w];
        atomicAdd(&g_loss, tt);
    }
}

// ---------------------------------------------------------------------------
// Update kernel: slerp + rms_norm codebook EMA (1 warp per code) + vq_loss.
// ---------------------------------------------------------------------------
__global__ void vq_update(const float* __restrict__ cb, float* __restrict__ out) {
    if (blockIdx.x == 0 && threadIdx.x == 0)
        out[LOSS_OFF] = 1.25f * g_loss * (1.0f / 8388608.0f);

    const int code = blockIdx.x * 8 + (threadIdx.x >> 5);
    const int lane = threadIdx.x & 31;
    if (code >= H * M) return;

    const float* old = cb + (size_t)code * D;
    float o0 = old[lane];
    float o1 = old[lane + 32];
    float cnt = g_counts[code];
    float r0, r1;

    if (cnt > 0.0f) {
        float m0 = g_sums[code * D + lane] / cnt;
        float m1 = g_sums[code * D + lane + 32] / cnt;

        float dot = m0 * o0 + m1 * o1;
        float nl  = m0 * m0 + m1 * m1;
        float nh  = o0 * o0 + o1 * o1;
#pragma unroll
        for (int o = 16; o > 0; o >>= 1) {
            dot += __shfl_xor_sync(0xffffffffu, dot, o);
            nl  += __shfl_xor_sync(0xffffffffu, nl,  o);
            nh  += __shfl_xor_sync(0xffffffffu, nh,  o);
        }
        float cosv = dot / fmaxf(sqrtf(nl) * sqrtf(nh), 1e-8f);
        cosv = fminf(fmaxf(cosv, (float)(-1.0 + 1e-7)), (float)(1.0 - 1e-7));
        float omega = acosf(cosv);
        float so = sinf(omega);
        float wl = sinf(0.01f * omega);
        float wh = sinf(0.99f * omega);
        r0 = (m0 * wl + o0 * wh) / so;
        r1 = (m1 * wl + o1 * wh) / so;

        float ss = r0 * r0 + r1 * r1;
#pragma unroll
        for (int o = 16; o > 0; o >>= 1)
            ss += __shfl_xor_sync(0xffffffffu, ss, o);
        float inv = 1.0f / sqrtf(ss * (1.0f / 64.0f) + 1.1920929e-07f);
        r0 *= inv;
        r1 *= inv;
    } else {
        r0 = o0;
        r1 = o1;
    }

    out[CB_OFF + (size_t)code * D + lane]      = r0;
    out[CB_OFF + (size_t)code * D + lane + 32] = r1;
}

// ---------------------------------------------------------------------------
extern "C" void kernel_launch(void* const* d_in, const int* in_sizes, int n_in,
                              void* d_out, int out_size) {
    const float* z  = (const float*)d_in[0];   // [8, 512, 2048]
    const float* cb = (const float*)d_in[1];   // [8, 1024, 64]
    float* out = (float*)d_out;

    cudaFuncSetAttribute(vq_main, cudaFuncAttributeMaxDynamicSharedMemorySize,
                         (int)sizeof(Smem));

    prep_b<<<512, 256>>>(cb);

    dim3 grid(NTOK / TOKC, H);
    vq_main<<<grid, 256, sizeof(Smem)>>>(z, cb, out);

    vq_update<<<H * M / 8, 256>>>(cb, out);

    // Reset scratch for the NEXT invocation (initial state is zero at load).
    zero_kernel<<<(H * M * D + 255) / 256, 256>>>();
}